// round 8
// baseline (speedup 1.0000x reference)
#include <cuda_runtime.h>
#include <cuda_bf16.h>
#include <math.h>
#include <stdint.h>

#define Nn   20000
#define Ee   320000
#define F_IN 512
#define HID  128
#define OUT  128
#define Hh   4
#define Cc   64
#define HC   256
#define TT   (Ee + Nn)   // edges incl. self loops

// ---------------- scratch (static device globals; no allocation) -------------
__device__ __align__(16) __nv_bfloat16 g_h1hi[Nn * HID];
__device__ __align__(16) __nv_bfloat16 g_h1lo[Nn * HID];
__device__ __align__(16) __nv_bfloat16 g_h2hi[Nn * OUT];
__device__ __align__(16) __nv_bfloat16 g_h2lo[Nn * OUT];
__device__ __align__(16) __nv_bfloat16 g_w1thi[HID * F_IN];
__device__ __align__(16) __nv_bfloat16 g_w1tlo[HID * F_IN];
__device__ __align__(16) __nv_bfloat16 g_w2thi[OUT * HID];
__device__ __align__(16) __nv_bfloat16 g_w2tlo[OUT * HID];
__device__ __align__(16) __nv_bfloat16 g_wgthi[HC * OUT];
__device__ __align__(16) __nv_bfloat16 g_wgtlo[HC * OUT];
__device__ __align__(16) float g_xg[Nn * HC];
__device__ __align__(16) float g_asrc[Nn * Hh];
__device__ __align__(16) float g_adst[Nn * Hh];
__device__ int g_cnt[Nn];
__device__ int g_off[Nn];
__device__ int g_cur[Nn];
__device__ int g_csr[TT];

// ---------------- mma / ldmatrix helpers ---------------------------------------
__device__ __forceinline__ uint32_t s2u(const void* p) {
    return (uint32_t)__cvta_generic_to_shared(p);
}

__device__ __forceinline__ void ldm_x4(uint32_t* r, uint32_t addr) {
    asm volatile("ldmatrix.sync.aligned.m8n8.x4.shared.b16 {%0,%1,%2,%3}, [%4];"
                 : "=r"(r[0]), "=r"(r[1]), "=r"(r[2]), "=r"(r[3]) : "r"(addr));
}
__device__ __forceinline__ void ldm_x2(uint32_t* r, uint32_t addr) {
    asm volatile("ldmatrix.sync.aligned.m8n8.x2.shared.b16 {%0,%1}, [%2];"
                 : "=r"(r[0]), "=r"(r[1]) : "r"(addr));
}

__device__ __forceinline__ void mma_bf16(float* c, const uint32_t* a, const uint32_t* b) {
    asm volatile("mma.sync.aligned.m16n8k16.row.col.f32.bf16.bf16.f32 "
                 "{%0,%1,%2,%3}, {%4,%5,%6,%7}, {%8,%9}, {%0,%1,%2,%3};"
                 : "+f"(c[0]), "+f"(c[1]), "+f"(c[2]), "+f"(c[3])
                 : "r"(a[0]), "r"(a[1]), "r"(a[2]), "r"(a[3]), "r"(b[0]), "r"(b[1]));
}

// split 8 fp32 -> 8 bf16 hi + 8 bf16 lo (packed into uint4 each)
__device__ __forceinline__ void split8(float4 a, float4 b, uint4& vh, uint4& vl) {
    const float f[8] = {a.x, a.y, a.z, a.w, b.x, b.y, b.z, b.w};
    uint32_t hw[4], lw[4];
#pragma unroll
    for (int i = 0; i < 4; i++) {
        const __nv_bfloat16 h0 = __float2bfloat16(f[2 * i]);
        const __nv_bfloat16 h1 = __float2bfloat16(f[2 * i + 1]);
        __nv_bfloat162 hp = __halves2bfloat162(h0, h1);
        hw[i] = *(uint32_t*)&hp;
        __nv_bfloat162 lp = __halves2bfloat162(
            __float2bfloat16(f[2 * i]     - __bfloat162float(h0)),
            __float2bfloat16(f[2 * i + 1] - __bfloat162float(h1)));
        lw[i] = *(uint32_t*)&lp;
    }
    vh = make_uint4(hw[0], hw[1], hw[2], hw[3]);
    vl = make_uint4(lw[0], lw[1], lw[2], lw[3]);
}

// ============ bf16x3 GEMM: C = op(A @ B^T + bias), fp32-class accuracy =========
// ASPLIT: A is fp32, split to hi/lo inline during tile fill.
// ATT: epilogue also accumulates a_src/a_dst = einsum(C, att_src/att_dst).
template<bool RELU, bool HAS_BIAS, bool OSPLIT, bool ASPLIT, bool ATT>
__global__ __launch_bounds__(256)
void bf16gemm(const float* __restrict__ Af,
              const __nv_bfloat16* __restrict__ Ahi,
              const __nv_bfloat16* __restrict__ Alo,
              const __nv_bfloat16* __restrict__ Bhi,
              const __nv_bfloat16* __restrict__ Blo,
              const float* __restrict__ bias,
              float* __restrict__ Cf,
              __nv_bfloat16* __restrict__ Chi,
              __nv_bfloat16* __restrict__ Clo,
              const float* __restrict__ att_s,
              const float* __restrict__ att_d,
              int M, int Nc, int K) {
    __shared__ __nv_bfloat16 Ash[128][40];   // +8 pad
    __shared__ __nv_bfloat16 Asl[128][40];
    __shared__ __nv_bfloat16 Bsh[128][40];
    __shared__ __nv_bfloat16 Bsl[128][40];

    const int tid  = threadIdx.x;
    const int lane = tid & 31;
    const int warp = tid >> 5;
    const int wm = warp & 1;          // 0..1 -> 64 rows
    const int wn = warp >> 1;         // 0..3 -> 32 cols
    const int g  = lane >> 2;         // 0..7
    const int t  = lane & 3;          // 0..3

    const int rowBase = blockIdx.y * 128;
    const int colBase = blockIdx.x * 128;

    float acc[4][4][4];
#pragma unroll
    for (int i = 0; i < 4; i++)
#pragma unroll
        for (int j = 0; j < 4; j++)
#pragma unroll
            for (int q = 0; q < 4; q++) acc[i][j][q] = 0.f;

    const int a_row = (lane & 7) + ((lane >> 3) & 1) * 8;   // 0..15
    const int a_kof = (lane >> 4) * 8;                      // 0 or 8
    const int b_row = lane & 7;
    const int b_kof = ((lane >> 3) & 1) * 8;

    for (int kt = 0; kt < K; kt += 32) {
#pragma unroll
        for (int c = 0; c < 2; c++) {
            const int id   = tid + c * 256;
            const int row  = id >> 2;
            const int part = (id & 3) * 8;
            const int gr   = rowBase + row;
            uint4 vh = make_uint4(0u, 0u, 0u, 0u), vl = vh;
            if (gr < M) {
                if (ASPLIT) {
                    const float* ap = Af + (size_t)gr * K + kt + part;
                    split8(*(const float4*)ap, *(const float4*)(ap + 4), vh, vl);
                } else {
                    vh = *(const uint4*)(Ahi + (size_t)gr * K + kt + part);
                    vl = *(const uint4*)(Alo + (size_t)gr * K + kt + part);
                }
            }
            *(uint4*)&Ash[row][part] = vh;
            *(uint4*)&Asl[row][part] = vl;
            const int gn = colBase + row;
            *(uint4*)&Bsh[row][part] = *(const uint4*)(Bhi + (size_t)gn * K + kt + part);
            *(uint4*)&Bsl[row][part] = *(const uint4*)(Blo + (size_t)gn * K + kt + part);
        }
        __syncthreads();

#pragma unroll
        for (int ka = 0; ka < 2; ka++) {
            const int k0 = ka * 16;
            uint32_t bhi[4][2], blo[4][2];
#pragma unroll
            for (int na = 0; na < 4; na++) {
                const int n0 = wn * 32 + na * 8;
                ldm_x2(bhi[na], s2u(&Bsh[n0 + b_row][k0 + b_kof]));
                ldm_x2(blo[na], s2u(&Bsl[n0 + b_row][k0 + b_kof]));
            }
#pragma unroll
            for (int ma = 0; ma < 4; ma++) {
                const int m0 = wm * 64 + ma * 16;
                uint32_t ahi[4], alo[4];
                ldm_x4(ahi, s2u(&Ash[m0 + a_row][k0 + a_kof]));
                ldm_x4(alo, s2u(&Asl[m0 + a_row][k0 + a_kof]));
#pragma unroll
                for (int na = 0; na < 4; na++) {
                    mma_bf16(acc[ma][na], ahi, bhi[na]);
                    mma_bf16(acc[ma][na], alo, bhi[na]);
                    mma_bf16(acc[ma][na], ahi, blo[na]);
                }
            }
        }
        __syncthreads();
    }

    // ---- epilogue stores: c0,c1 -> (row g, col 2t), c2,c3 -> (row g+8) ----
#pragma unroll
    for (int na = 0; na < 4; na++) {
        const int c = colBase + wn * 32 + na * 8 + 2 * t;
        float2 bb = make_float2(0.f, 0.f);
        if (HAS_BIAS) bb = *(const float2*)(bias + c);
#pragma unroll
        for (int ma = 0; ma < 4; ma++) {
            const int r0 = rowBase + wm * 64 + ma * 16 + g;
            float v0 = acc[ma][na][0] + bb.x;
            float v1 = acc[ma][na][1] + bb.y;
            float v2 = acc[ma][na][2] + bb.x;
            float v3 = acc[ma][na][3] + bb.y;
            if (RELU) {
                v0 = fmaxf(v0, 0.f); v1 = fmaxf(v1, 0.f);
                v2 = fmaxf(v2, 0.f); v3 = fmaxf(v3, 0.f);
            }
            if (OSPLIT) {
                if (r0 < M) {
                    const __nv_bfloat16 h0 = __float2bfloat16(v0);
                    const __nv_bfloat16 h1 = __float2bfloat16(v1);
                    *(__nv_bfloat162*)(Chi + (size_t)r0 * Nc + c) = __halves2bfloat162(h0, h1);
                    *(__nv_bfloat162*)(Clo + (size_t)r0 * Nc + c) =
                        __halves2bfloat162(__float2bfloat16(v0 - __bfloat162float(h0)),
                                           __float2bfloat16(v1 - __bfloat162float(h1)));
                }
                if (r0 + 8 < M) {
                    const __nv_bfloat16 h2 = __float2bfloat16(v2);
                    const __nv_bfloat16 h3 = __float2bfloat16(v3);
                    *(__nv_bfloat162*)(Chi + (size_t)(r0 + 8) * Nc + c) = __halves2bfloat162(h2, h3);
                    *(__nv_bfloat162*)(Clo + (size_t)(r0 + 8) * Nc + c) =
                        __halves2bfloat162(__float2bfloat16(v2 - __bfloat162float(h2)),
                                           __float2bfloat16(v3 - __bfloat162float(h3)));
                }
            } else {
                if (r0 < M)     *(float2*)(Cf + (size_t)r0 * Nc + c)       = make_float2(v0, v1);
                if (r0 + 8 < M) *(float2*)(Cf + (size_t)(r0 + 8) * Nc + c) = make_float2(v2, v3);
            }
        }
    }

    // ---- fused attention coefficients (G3 only) ----
    if (ATT) {
        const int h = (colBase + wn * 32) >> 6;     // this warp's head
        float asv[4][2], adv[4][2];
#pragma unroll
        for (int na = 0; na < 4; na++) {
            const int cc = (wn * 32 + na * 8 + 2 * t) & 63;
            asv[na][0] = __ldg(att_s + h * Cc + cc);
            asv[na][1] = __ldg(att_s + h * Cc + cc + 1);
            adv[na][0] = __ldg(att_d + h * Cc + cc);
            adv[na][1] = __ldg(att_d + h * Cc + cc + 1);
        }
#pragma unroll
        for (int ma = 0; ma < 4; ma++) {
            const int r0 = rowBase + wm * 64 + ma * 16 + g;
            float ps0 = 0.f, pd0 = 0.f, ps1 = 0.f, pd1 = 0.f;
#pragma unroll
            for (int na = 0; na < 4; na++) {
                ps0 += acc[ma][na][0] * asv[na][0] + acc[ma][na][1] * asv[na][1];
                pd0 += acc[ma][na][0] * adv[na][0] + acc[ma][na][1] * adv[na][1];
                ps1 += acc[ma][na][2] * asv[na][0] + acc[ma][na][3] * asv[na][1];
                pd1 += acc[ma][na][2] * adv[na][0] + acc[ma][na][3] * adv[na][1];
            }
#pragma unroll
            for (int o = 2; o >= 1; o >>= 1) {
                ps0 += __shfl_down_sync(0xffffffffu, ps0, o);
                pd0 += __shfl_down_sync(0xffffffffu, pd0, o);
                ps1 += __shfl_down_sync(0xffffffffu, ps1, o);
                pd1 += __shfl_down_sync(0xffffffffu, pd1, o);
            }
            if (t == 0) {
                if (r0 < M) {
                    atomicAdd(&g_asrc[r0 * Hh + h], ps0);
                    atomicAdd(&g_adst[r0 * Hh + h], pd0);
                }
                if (r0 + 8 < M) {
                    atomicAdd(&g_asrc[(r0 + 8) * Hh + h], ps1);
                    atomicAdd(&g_adst[(r0 + 8) * Hh + h], pd1);
                }
            }
        }
    }
}

// ---------------- prep: W[K,N] -> transposed split [N,K] ----------------------
__global__ void wtsplit_kernel(const float* __restrict__ W,
                               __nv_bfloat16* __restrict__ thi,
                               __nv_bfloat16* __restrict__ tlo, int K, int N) {
    const int i = blockIdx.x * blockDim.x + threadIdx.x;
    if (i >= K * N) return;
    const int n = i / K, k = i % K;
    const float v = W[(size_t)k * N + n];
    const __nv_bfloat16 h = __float2bfloat16(v);
    thi[i] = h;
    tlo[i] = __float2bfloat16(v - __bfloat162float(h));
}

// ---------------- init: cnt = 1 (self loop), asrc/adst = 0 --------------------
__global__ void zero_kernel() {
    const int i = blockIdx.x * blockDim.x + threadIdx.x;
    if (i < Nn) g_cnt[i] = 1;
    if (i < Nn * Hh) { g_asrc[i] = 0.f; g_adst[i] = 0.f; }
}

__global__ void count_kernel(const int* __restrict__ ei) {
    const int e = blockIdx.x * blockDim.x + threadIdx.x;
    if (e < Ee) atomicAdd(&g_cnt[ei[Ee + e]], 1);
}

__global__ __launch_bounds__(1024)
void scan_kernel() {
    __shared__ int part[1024];
    const int t = threadIdx.x;
    const int CH = (Nn + 1023) / 1024;   // 20
    const int base = t * CH;
    int s = 0;
    for (int i = 0; i < CH; i++) {
        const int idx = base + i;
        if (idx < Nn) s += g_cnt[idx];
    }
    part[t] = s;
    __syncthreads();
    for (int off = 1; off < 1024; off <<= 1) {
        int v = 0;
        if (t >= off) v = part[t - off];
        __syncthreads();
        if (t >= off) part[t] += v;
        __syncthreads();
    }
    int run = (t == 0) ? 0 : part[t - 1];
    for (int i = 0; i < CH; i++) {
        const int idx = base + i;
        if (idx < Nn) {
            const int c = g_cnt[idx];
            g_off[idx] = run;
            g_cur[idx] = run;
            run += c;
        }
    }
}

__global__ void scatter_kernel(const int* __restrict__ ei) {
    const int e = blockIdx.x * blockDim.x + threadIdx.x;
    if (e >= TT) return;
    int src, dst;
    if (e < Ee) { src = ei[e]; dst = ei[Ee + e]; }
    else        { src = dst = e - Ee; }
    const int pos = atomicAdd(&g_cur[dst], 1);
    g_csr[pos] = src;
}

// ---------------- fused GAT softmax + aggregation: one warp per dst -----------
__global__ void gat_agg_kernel(float* __restrict__ out,
                               const float* __restrict__ bias_g) {
    const int d    = (blockIdx.x * blockDim.x + threadIdx.x) >> 5;
    const int lane = threadIdx.x & 31;
    if (d >= Nn) return;

    const int start = g_off[d];
    const int deg   = g_cnt[d];

    const float4 ad = *(const float4*)(g_adst + d * 4);

    float4 sum = make_float4(0.f, 0.f, 0.f, 0.f);
    for (int k = lane; k < deg; k += 32) {
        const int s = g_csr[start + k];
        const float4 as = *(const float4*)(g_asrc + s * 4);
        float ex = as.x + ad.x, ey = as.y + ad.y, ez = as.z + ad.z, ew = as.w + ad.w;
        ex = ex > 0.f ? ex : 0.2f * ex;
        ey = ey > 0.f ? ey : 0.2f * ey;
        ez = ez > 0.f ? ez : 0.2f * ez;
        ew = ew > 0.f ? ew : 0.2f * ew;
        sum.x += expf(ex);
        sum.y += expf(ey);
        sum.z += expf(ez);
        sum.w += expf(ew);
    }
#pragma unroll
    for (int o = 16; o > 0; o >>= 1) {
        sum.x += __shfl_down_sync(0xffffffffu, sum.x, o);
        sum.y += __shfl_down_sync(0xffffffffu, sum.y, o);
        sum.z += __shfl_down_sync(0xffffffffu, sum.z, o);
        sum.w += __shfl_down_sync(0xffffffffu, sum.w, o);
    }
    const float dx = __shfl_sync(0xffffffffu, sum.x, 0) + 1e-16f;
    const float dy = __shfl_sync(0xffffffffu, sum.y, 0) + 1e-16f;
    const float dz = __shfl_sync(0xffffffffu, sum.z, 0) + 1e-16f;
    const float dw = __shfl_sync(0xffffffffu, sum.w, 0) + 1e-16f;

    const int h = lane >> 3;
    const float adh   = (h == 0) ? ad.x : (h == 1) ? ad.y : (h == 2) ? ad.z : ad.w;
    const float denom = (h == 0) ? dx   : (h == 1) ? dy   : (h == 2) ? dz   : dw;
    const float rden  = 1.f / denom;

    float acc[8];
#pragma unroll
    for (int i = 0; i < 8; i++) acc[i] = 0.f;

    int k = 0;
    for (; k + 2 <= deg; k += 2) {
        const int s0 = g_csr[start + k];
        const int s1 = g_csr[start + k + 1];
        float e0 = g_asrc[s0 * 4 + h] + adh;
        float e1 = g_asrc[s1 * 4 + h] + adh;
        e0 = e0 > 0.f ? e0 : 0.2f * e0;
        e1 = e1 > 0.f ? e1 : 0.2f * e1;
        const float al0 = expf(e0) * rden;
        const float al1 = expf(e1) * rden;
        const float4* x0 = (const float4*)(g_xg + (size_t)s0 * HC + lane * 8);
        const float4* x1 = (const float4*)(g_xg + (size_t)s1 * HC + lane * 8);
        const float4 a0 = x0[0], a1 = x0[1];
        const float4 b0 = x1[0], b1 = x1[1];
        acc[0] = fmaf(al0, a0.x, fmaf(al1, b0.x, acc[0]));
        acc[1] = fmaf(al0, a0.y, fmaf(al1, b0.y, acc[1]));
        acc[2] = fmaf(al0, a0.z, fmaf(al1, b0.z, acc[2]));
        acc[3] = fmaf(al0, a0.w, fmaf(al1, b0.w, acc[3]));
        acc[4] = fmaf(al0, a1.x, fmaf(al1, b1.x, acc[4]));
        acc[5] = fmaf(al0, a1.y, fmaf(al1, b1.y, acc[5]));
        acc[6] = fmaf(al0, a1.z, fmaf(al1, b1.z, acc[6]));
        acc[7] = fmaf(al0, a1.w, fmaf(al1, b1.w, acc[7]));
    }
    if (k < deg) {
        const int s = g_csr[start + k];
        float e = g_asrc[s * 4 + h] + adh;
        e = e > 0.f ? e : 0.2f * e;
        const float alpha = expf(e) * rden;
        const float4* xr = (const float4*)(g_xg + (size_t)s * HC + lane * 8);
        const float4 v0 = xr[0];
        const float4 v1 = xr[1];
        acc[0] = fmaf(alpha, v0.x, acc[0]);
        acc[1] = fmaf(alpha, v0.y, acc[1]);
        acc[2] = fmaf(alpha, v0.z, acc[2]);
        acc[3] = fmaf(alpha, v0.w, acc[3]);
        acc[4] = fmaf(alpha, v1.x, acc[4]);
        acc[5] = fmaf(alpha, v1.y, acc[5]);
        acc[6] = fmaf(alpha, v1.z, acc[6]);
        acc[7] = fmaf(alpha, v1.w, acc[7]);
    }

    const float4 bg0 = *(const float4*)(bias_g + lane * 8);
    const float4 bg1 = *(const float4*)(bias_g + lane * 8 + 4);
    float* op = out + (size_t)d * HC + lane * 8;
    *(float4*)op       = make_float4(acc[0] + bg0.x, acc[1] + bg0.y,
                                     acc[2] + bg0.z, acc[3] + bg0.w);
    *(float4*)(op + 4) = make_float4(acc[4] + bg1.x, acc[5] + bg1.y,
                                     acc[6] + bg1.z, acc[7] + bg1.w);
}

// ---------------- launch --------------------------------------------------------
extern "C" void kernel_launch(void* const* d_in, const int* in_sizes, int n_in,
                              void* d_out, int out_size) {
    const float* x   = (const float*)d_in[0];
    const int*   ei  = (const int*)d_in[1];
    const float* W1  = (const float*)d_in[2];
    const float* b1  = (const float*)d_in[3];
    const float* W2  = (const float*)d_in[4];
    const float* b2  = (const float*)d_in[5];
    const float* Wg  = (const float*)d_in[6];
    const float* att_src = (const float*)d_in[7];
    const float* att_dst = (const float*)d_in[8];
    const float* bias_g  = (const float*)d_in[9];
    float* out = (float*)d_out;

    __nv_bfloat16 *h1hi, *h1lo, *h2hi, *h2lo;
    __nv_bfloat16 *w1thi, *w1tlo, *w2thi, *w2tlo, *wgthi, *wgtlo;
    float* xg;
    cudaGetSymbolAddress((void**)&h1hi, g_h1hi);
    cudaGetSymbolAddress((void**)&h1lo, g_h1lo);
    cudaGetSymbolAddress((void**)&h2hi, g_h2hi);
    cudaGetSymbolAddress((void**)&h2lo, g_h2lo);
    cudaGetSymbolAddress((void**)&w1thi, g_w1thi);
    cudaGetSymbolAddress((void**)&w1tlo, g_w1tlo);
    cudaGetSymbolAddress((void**)&w2thi, g_w2thi);
    cudaGetSymbolAddress((void**)&w2tlo, g_w2tlo);
    cudaGetSymbolAddress((void**)&wgthi, g_wgthi);
    cudaGetSymbolAddress((void**)&wgtlo, g_wgtlo);
    cudaGetSymbolAddress((void**)&xg, g_xg);

    const int mblk = (Nn + 127) / 128;   // 157

    // init (counts + att accumulators)
    zero_kernel<<<(Nn * Hh + 255) / 256, 256>>>();

    // CSR build
    count_kernel<<<(Ee + 255) / 256, 256>>>(ei);
    scan_kernel<<<1, 1024>>>();
    scatter_kernel<<<(TT + 255) / 256, 256>>>(ei);

    // prep: transpose+split weights
    wtsplit_kernel<<<(F_IN * HID + 255) / 256, 256>>>(W1, w1thi, w1tlo, F_IN, HID);
    wtsplit_kernel<<<(HID * OUT + 255) / 256, 256>>>(W2, w2thi, w2tlo, HID, OUT);
    wtsplit_kernel<<<(OUT * HC + 255) / 256, 256>>>(Wg, wgthi, wgtlo, OUT, HC);

    // GEMM chain (bf16x3 on mma.sync.m16n8k16)
    bf16gemm<true,  true,  true,  true,  false><<<dim3(1, mblk), 256>>>(
        x, nullptr, nullptr, w1thi, w1tlo, b1,
        nullptr, h1hi, h1lo, nullptr, nullptr, Nn, HID, F_IN);
    bf16gemm<false, true,  true,  false, false><<<dim3(1, mblk), 256>>>(
        nullptr, h1hi, h1lo, w2thi, w2tlo, b2,
        nullptr, h2hi, h2lo, nullptr, nullptr, Nn, OUT, HID);
    bf16gemm<false, false, false, false, true ><<<dim3(2, mblk), 256>>>(
        nullptr, h2hi, h2lo, wgthi, wgtlo, nullptr,
        xg, nullptr, nullptr, att_src, att_dst, Nn, HC, OUT);

    // fused softmax + aggregation
    gat_agg_kernel<<<(Nn + 7) / 8, 256>>>(out, bias_g);
}

// round 9
// speedup vs baseline: 1.0927x; 1.0927x over previous
#include <cuda_runtime.h>
#include <cuda_bf16.h>
#include <math.h>
#include <stdint.h>

#define Nn   20000
#define Ee   320000
#define F_IN 512
#define HID  128
#define OUT  128
#define Hh   4
#define Cc   64
#define HC   256
#define TT   (Ee + Nn)   // edges incl. self loops

// ---------------- scratch (static device globals; no allocation) -------------
__device__ __align__(16) __nv_bfloat16 g_xhi[Nn * F_IN];
__device__ __align__(16) __nv_bfloat16 g_xlo[Nn * F_IN];
__device__ __align__(16) __nv_bfloat16 g_h1hi[Nn * HID];
__device__ __align__(16) __nv_bfloat16 g_h1lo[Nn * HID];
__device__ __align__(16) __nv_bfloat16 g_h2hi[Nn * OUT];
__device__ __align__(16) __nv_bfloat16 g_h2lo[Nn * OUT];
__device__ __align__(16) __nv_bfloat16 g_w1thi[HID * F_IN];
__device__ __align__(16) __nv_bfloat16 g_w1tlo[HID * F_IN];
__device__ __align__(16) __nv_bfloat16 g_w2thi[OUT * HID];
__device__ __align__(16) __nv_bfloat16 g_w2tlo[OUT * HID];
__device__ __align__(16) __nv_bfloat16 g_wgthi[HC * OUT];
__device__ __align__(16) __nv_bfloat16 g_wgtlo[HC * OUT];
__device__ __align__(16) float g_xg[Nn * HC];
__device__ __align__(16) float g_asrc[Nn * Hh];
__device__ __align__(16) float g_adst[Nn * Hh];
__device__ __align__(16) float g_alpha[TT * Hh];
__device__ int g_cnt[Nn];
__device__ int g_off[Nn];
__device__ int g_cur[Nn];
__device__ int g_csr[TT];

// ---------------- mma / ldmatrix helpers ---------------------------------------
__device__ __forceinline__ uint32_t s2u(const void* p) {
    return (uint32_t)__cvta_generic_to_shared(p);
}

__device__ __forceinline__ void ldm_x4(uint32_t* r, uint32_t addr) {
    asm volatile("ldmatrix.sync.aligned.m8n8.x4.shared.b16 {%0,%1,%2,%3}, [%4];"
                 : "=r"(r[0]), "=r"(r[1]), "=r"(r[2]), "=r"(r[3]) : "r"(addr));
}
__device__ __forceinline__ void ldm_x2(uint32_t* r, uint32_t addr) {
    asm volatile("ldmatrix.sync.aligned.m8n8.x2.shared.b16 {%0,%1}, [%2];"
                 : "=r"(r[0]), "=r"(r[1]) : "r"(addr));
}

__device__ __forceinline__ void mma_bf16(float* c, const uint32_t* a, const uint32_t* b) {
    asm volatile("mma.sync.aligned.m16n8k16.row.col.f32.bf16.bf16.f32 "
                 "{%0,%1,%2,%3}, {%4,%5,%6,%7}, {%8,%9}, {%0,%1,%2,%3};"
                 : "+f"(c[0]), "+f"(c[1]), "+f"(c[2]), "+f"(c[3])
                 : "r"(a[0]), "r"(a[1]), "r"(a[2]), "r"(a[3]), "r"(b[0]), "r"(b[1]));
}

// ============ bf16x3 GEMM: C = op(A @ B^T + bias), fp32-class accuracy =========
// A pre-split bf16 hi/lo [M,K] row-major; B pre-split+transposed [Nc,K].
// Block 128x128, BK=32; 8 warps 2(M)x4(N); warp tile 64x32.
template<bool RELU, bool HAS_BIAS, bool OSPLIT>
__global__ __launch_bounds__(256)
void bf16gemm(const __nv_bfloat16* __restrict__ Ahi,
              const __nv_bfloat16* __restrict__ Alo,
              const __nv_bfloat16* __restrict__ Bhi,
              const __nv_bfloat16* __restrict__ Blo,
              const float* __restrict__ bias,
              float* __restrict__ Cf,
              __nv_bfloat16* __restrict__ Chi,
              __nv_bfloat16* __restrict__ Clo,
              int M, int Nc, int K) {
    __shared__ __nv_bfloat16 Ash[128][40];   // +8 pad
    __shared__ __nv_bfloat16 Asl[128][40];
    __shared__ __nv_bfloat16 Bsh[128][40];
    __shared__ __nv_bfloat16 Bsl[128][40];

    const int tid  = threadIdx.x;
    const int lane = tid & 31;
    const int warp = tid >> 5;
    const int wm = warp & 1;          // 0..1 -> 64 rows
    const int wn = warp >> 1;         // 0..3 -> 32 cols
    const int g  = lane >> 2;         // 0..7
    const int t  = lane & 3;          // 0..3

    const int rowBase = blockIdx.y * 128;
    const int colBase = blockIdx.x * 128;

    float acc[4][4][4];
#pragma unroll
    for (int i = 0; i < 4; i++)
#pragma unroll
        for (int j = 0; j < 4; j++)
#pragma unroll
            for (int q = 0; q < 4; q++) acc[i][j][q] = 0.f;

    const int a_row = (lane & 7) + ((lane >> 3) & 1) * 8;   // 0..15
    const int a_kof = (lane >> 4) * 8;                      // 0 or 8
    const int b_row = lane & 7;
    const int b_kof = ((lane >> 3) & 1) * 8;

    for (int kt = 0; kt < K; kt += 32) {
#pragma unroll
        for (int c = 0; c < 2; c++) {
            const int id   = tid + c * 256;
            const int row  = id >> 2;
            const int part = (id & 3) * 8;
            const int gr   = rowBase + row;
            uint4 vh = make_uint4(0u, 0u, 0u, 0u), vl = vh;
            if (gr < M) {
                vh = *(const uint4*)(Ahi + (size_t)gr * K + kt + part);
                vl = *(const uint4*)(Alo + (size_t)gr * K + kt + part);
            }
            *(uint4*)&Ash[row][part] = vh;
            *(uint4*)&Asl[row][part] = vl;
            const int gn = colBase + row;
            *(uint4*)&Bsh[row][part] = *(const uint4*)(Bhi + (size_t)gn * K + kt + part);
            *(uint4*)&Bsl[row][part] = *(const uint4*)(Blo + (size_t)gn * K + kt + part);
        }
        __syncthreads();

#pragma unroll
        for (int ka = 0; ka < 2; ka++) {
            const int k0 = ka * 16;
            uint32_t bhi[4][2], blo[4][2];
#pragma unroll
            for (int na = 0; na < 4; na++) {
                const int n0 = wn * 32 + na * 8;
                ldm_x2(bhi[na], s2u(&Bsh[n0 + b_row][k0 + b_kof]));
                ldm_x2(blo[na], s2u(&Bsl[n0 + b_row][k0 + b_kof]));
            }
#pragma unroll
            for (int ma = 0; ma < 4; ma++) {
                const int m0 = wm * 64 + ma * 16;
                uint32_t ahi[4], alo[4];
                ldm_x4(ahi, s2u(&Ash[m0 + a_row][k0 + a_kof]));
                ldm_x4(alo, s2u(&Asl[m0 + a_row][k0 + a_kof]));
#pragma unroll
                for (int na = 0; na < 4; na++) {
                    mma_bf16(acc[ma][na], ahi, bhi[na]);
                    mma_bf16(acc[ma][na], alo, bhi[na]);
                    mma_bf16(acc[ma][na], ahi, blo[na]);
                }
            }
        }
        __syncthreads();
    }

    // ---- epilogue: c0,c1 -> (row g, col 2t), c2,c3 -> (row g+8, col 2t) ----
#pragma unroll
    for (int na = 0; na < 4; na++) {
        const int c = colBase + wn * 32 + na * 8 + 2 * t;
        float2 bb = make_float2(0.f, 0.f);
        if (HAS_BIAS) bb = *(const float2*)(bias + c);
#pragma unroll
        for (int ma = 0; ma < 4; ma++) {
            const int r0 = rowBase + wm * 64 + ma * 16 + g;
            float v0 = acc[ma][na][0] + bb.x;
            float v1 = acc[ma][na][1] + bb.y;
            float v2 = acc[ma][na][2] + bb.x;
            float v3 = acc[ma][na][3] + bb.y;
            if (RELU) {
                v0 = fmaxf(v0, 0.f); v1 = fmaxf(v1, 0.f);
                v2 = fmaxf(v2, 0.f); v3 = fmaxf(v3, 0.f);
            }
            if (OSPLIT) {
                if (r0 < M) {
                    const __nv_bfloat16 h0 = __float2bfloat16(v0);
                    const __nv_bfloat16 h1 = __float2bfloat16(v1);
                    *(__nv_bfloat162*)(Chi + (size_t)r0 * Nc + c) = __halves2bfloat162(h0, h1);
                    *(__nv_bfloat162*)(Clo + (size_t)r0 * Nc + c) =
                        __halves2bfloat162(__float2bfloat16(v0 - __bfloat162float(h0)),
                                           __float2bfloat16(v1 - __bfloat162float(h1)));
                }
                if (r0 + 8 < M) {
                    const __nv_bfloat16 h2 = __float2bfloat16(v2);
                    const __nv_bfloat16 h3 = __float2bfloat16(v3);
                    *(__nv_bfloat162*)(Chi + (size_t)(r0 + 8) * Nc + c) = __halves2bfloat162(h2, h3);
                    *(__nv_bfloat162*)(Clo + (size_t)(r0 + 8) * Nc + c) =
                        __halves2bfloat162(__float2bfloat16(v2 - __bfloat162float(h2)),
                                           __float2bfloat16(v3 - __bfloat162float(h3)));
                }
            } else {
                if (r0 < M)     *(float2*)(Cf + (size_t)r0 * Nc + c)       = make_float2(v0, v1);
                if (r0 + 8 < M) *(float2*)(Cf + (size_t)(r0 + 8) * Nc + c) = make_float2(v2, v3);
            }
        }
    }
}

// ---------------- prep: fp32 -> bf16 hi/lo split ------------------------------
__global__ void split_kernel(const float* __restrict__ src,
                             __nv_bfloat16* __restrict__ hi,
                             __nv_bfloat16* __restrict__ lo, int n4) {
    const int i = blockIdx.x * blockDim.x + threadIdx.x;
    if (i >= n4) return;
    const float4 v = *(const float4*)(src + (size_t)i * 4);
    const __nv_bfloat16 h0 = __float2bfloat16(v.x), h1 = __float2bfloat16(v.y);
    const __nv_bfloat16 h2 = __float2bfloat16(v.z), h3 = __float2bfloat16(v.w);
    __nv_bfloat162* hp = (__nv_bfloat162*)(hi + (size_t)i * 4);
    hp[0] = __halves2bfloat162(h0, h1);
    hp[1] = __halves2bfloat162(h2, h3);
    __nv_bfloat162* lp = (__nv_bfloat162*)(lo + (size_t)i * 4);
    lp[0] = __halves2bfloat162(__float2bfloat16(v.x - __bfloat162float(h0)),
                               __float2bfloat16(v.y - __bfloat162float(h1)));
    lp[1] = __halves2bfloat162(__float2bfloat16(v.z - __bfloat162float(h2)),
                               __float2bfloat16(v.w - __bfloat162float(h3)));
}

// ---------------- prep: W[K,N] -> transposed split [N,K] ----------------------
__global__ void wtsplit_kernel(const float* __restrict__ W,
                               __nv_bfloat16* __restrict__ thi,
                               __nv_bfloat16* __restrict__ tlo, int K, int N) {
    const int i = blockIdx.x * blockDim.x + threadIdx.x;
    if (i >= K * N) return;
    const int n = i / K, k = i % K;
    const float v = W[(size_t)k * N + n];
    const __nv_bfloat16 h = __float2bfloat16(v);
    thi[i] = h;
    tlo[i] = __float2bfloat16(v - __bfloat162float(h));
}

// ---------------- attention coefficients --------------------------------------
__global__ void att_kernel(const float* __restrict__ att_src,
                           const float* __restrict__ att_dst) {
    const int warp = (blockIdx.x * blockDim.x + threadIdx.x) >> 5;
    const int lane = threadIdx.x & 31;
    if (warp >= Nn * Hh) return;
    const int n = warp >> 2;
    const int h = warp & 3;
    const float* xr = g_xg + (size_t)n * HC + h * Cc;
    const float v0 = xr[lane];
    const float v1 = xr[lane + 32];
    float ss = v0 * __ldg(att_src + h * Cc + lane) + v1 * __ldg(att_src + h * Cc + lane + 32);
    float sd = v0 * __ldg(att_dst + h * Cc + lane) + v1 * __ldg(att_dst + h * Cc + lane + 32);
#pragma unroll
    for (int o = 16; o > 0; o >>= 1) {
        ss += __shfl_down_sync(0xffffffffu, ss, o);
        sd += __shfl_down_sync(0xffffffffu, sd, o);
    }
    if (lane == 0) {
        g_asrc[n * Hh + h] = ss;
        g_adst[n * Hh + h] = sd;
    }
}

// ---------------- CSR build ----------------------------------------------------
__global__ void init_counts_kernel() {
    const int i = blockIdx.x * blockDim.x + threadIdx.x;
    if (i < Nn) g_cnt[i] = 1;   // self loop
}

__global__ void count_kernel(const int* __restrict__ ei) {
    const int e = blockIdx.x * blockDim.x + threadIdx.x;
    if (e < Ee) atomicAdd(&g_cnt[ei[Ee + e]], 1);
}

__global__ __launch_bounds__(1024)
void scan_kernel() {
    __shared__ int part[1024];
    const int t = threadIdx.x;
    const int CH = (Nn + 1023) / 1024;   // 20
    const int base = t * CH;
    int s = 0;
    for (int i = 0; i < CH; i++) {
        const int idx = base + i;
        if (idx < Nn) s += g_cnt[idx];
    }
    part[t] = s;
    __syncthreads();
    for (int off = 1; off < 1024; off <<= 1) {
        int v = 0;
        if (t >= off) v = part[t - off];
        __syncthreads();
        if (t >= off) part[t] += v;
        __syncthreads();
    }
    int run = (t == 0) ? 0 : part[t - 1];
    for (int i = 0; i < CH; i++) {
        const int idx = base + i;
        if (idx < Nn) {
            const int c = g_cnt[idx];
            g_off[idx] = run;
            g_cur[idx] = run;
            run += c;
        }
    }
}

__global__ void scatter_kernel(const int* __restrict__ ei) {
    const int e = blockIdx.x * blockDim.x + threadIdx.x;
    if (e >= TT) return;
    int src, dst;
    if (e < Ee) { src = ei[e]; dst = ei[Ee + e]; }
    else        { src = dst = e - Ee; }
    const int pos = atomicAdd(&g_cur[dst], 1);
    g_csr[pos] = src;
}

// ---------------- fused GAT softmax + aggregation: one warp per dst -----------
// Pass 1 computes per-edge exp once (all 4 heads), caches to g_alpha, reduces
// denominators. Pass 2 is pure gather+FMA: no expf, no asrc loads.
__global__ void gat_agg_kernel(float* __restrict__ out,
                               const float* __restrict__ bias_g) {
    const int d    = (blockIdx.x * blockDim.x + threadIdx.x) >> 5;
    const int lane = threadIdx.x & 31;
    if (d >= Nn) return;

    const int start = g_off[d];
    const int deg   = g_cnt[d];

    const float4 ad = *(const float4*)(g_adst + d * 4);

    // --- pass 1: exp cache + denominators ---
    float4 sum = make_float4(0.f, 0.f, 0.f, 0.f);
    for (int k = lane; k < deg; k += 32) {
        const int s = g_csr[start + k];
        const float4 as = *(const float4*)(g_asrc + s * 4);
        float ex = as.x + ad.x, ey = as.y + ad.y, ez = as.z + ad.z, ew = as.w + ad.w;
        ex = ex > 0.f ? ex : 0.2f * ex;
        ey = ey > 0.f ? ey : 0.2f * ey;
        ez = ez > 0.f ? ez : 0.2f * ez;
        ew = ew > 0.f ? ew : 0.2f * ew;
        const float4 exv = make_float4(__expf(ex), __expf(ey), __expf(ez), __expf(ew));
        *(float4*)(g_alpha + (size_t)(start + k) * 4) = exv;
        sum.x += exv.x; sum.y += exv.y; sum.z += exv.z; sum.w += exv.w;
    }
#pragma unroll
    for (int o = 16; o > 0; o >>= 1) {
        sum.x += __shfl_down_sync(0xffffffffu, sum.x, o);
        sum.y += __shfl_down_sync(0xffffffffu, sum.y, o);
        sum.z += __shfl_down_sync(0xffffffffu, sum.z, o);
        sum.w += __shfl_down_sync(0xffffffffu, sum.w, o);
    }
    const float dx = __shfl_sync(0xffffffffu, sum.x, 0) + 1e-16f;
    const float dy = __shfl_sync(0xffffffffu, sum.y, 0) + 1e-16f;
    const float dz = __shfl_sync(0xffffffffu, sum.z, 0) + 1e-16f;
    const float dw = __shfl_sync(0xffffffffu, sum.w, 0) + 1e-16f;

    const int h = lane >> 3;   // 8 lanes per head
    const float denom = (h == 0) ? dx : (h == 1) ? dy : (h == 2) ? dz : dw;
    const float rden  = 1.f / denom;

    float acc[8];
#pragma unroll
    for (int i = 0; i < 8; i++) acc[i] = 0.f;

    // --- pass 2: pure gather + FMA, 4x unrolled ---
    const float* al = g_alpha + (size_t)start * 4;
    int k = 0;
    for (; k + 4 <= deg; k += 4) {
        const int s0 = g_csr[start + k];
        const int s1 = g_csr[start + k + 1];
        const int s2 = g_csr[start + k + 2];
        const int s3 = g_csr[start + k + 3];
        const float a0 = al[(k    ) * 4 + h] * rden;
        const float a1 = al[(k + 1) * 4 + h] * rden;
        const float a2 = al[(k + 2) * 4 + h] * rden;
        const float a3 = al[(k + 3) * 4 + h] * rden;
        const float4* x0 = (const float4*)(g_xg + (size_t)s0 * HC + lane * 8);
        const float4* x1 = (const float4*)(g_xg + (size_t)s1 * HC + lane * 8);
        const float4* x2 = (const float4*)(g_xg + (size_t)s2 * HC + lane * 8);
        const float4* x3 = (const float4*)(g_xg + (size_t)s3 * HC + lane * 8);
        const float4 p0 = x0[0], q0 = x0[1];
        const float4 p1 = x1[0], q1 = x1[1];
        const float4 p2 = x2[0], q2 = x2[1];
        const float4 p3 = x3[0], q3 = x3[1];
        acc[0] = fmaf(a0, p0.x, fmaf(a1, p1.x, fmaf(a2, p2.x, fmaf(a3, p3.x, acc[0]))));
        acc[1] = fmaf(a0, p0.y, fmaf(a1, p1.y, fmaf(a2, p2.y, fmaf(a3, p3.y, acc[1]))));
        acc[2] = fmaf(a0, p0.z, fmaf(a1, p1.z, fmaf(a2, p2.z, fmaf(a3, p3.z, acc[2]))));
        acc[3] = fmaf(a0, p0.w, fmaf(a1, p1.w, fmaf(a2, p2.w, fmaf(a3, p3.w, acc[3]))));
        acc[4] = fmaf(a0, q0.x, fmaf(a1, q1.x, fmaf(a2, q2.x, fmaf(a3, q3.x, acc[4]))));
        acc[5] = fmaf(a0, q0.y, fmaf(a1, q1.y, fmaf(a2, q2.y, fmaf(a3, q3.y, acc[5]))));
        acc[6] = fmaf(a0, q0.z, fmaf(a1, q1.z, fmaf(a2, q2.z, fmaf(a3, q3.z, acc[6]))));
        acc[7] = fmaf(a0, q0.w, fmaf(a1, q1.w, fmaf(a2, q2.w, fmaf(a3, q3.w, acc[7]))));
    }
    for (; k < deg; k++) {
        const int s = g_csr[start + k];
        const float a = al[k * 4 + h] * rden;
        const float4* xr = (const float4*)(g_xg + (size_t)s * HC + lane * 8);
        const float4 v0 = xr[0];
        const float4 v1 = xr[1];
        acc[0] = fmaf(a, v0.x, acc[0]);
        acc[1] = fmaf(a, v0.y, acc[1]);
        acc[2] = fmaf(a, v0.z, acc[2]);
        acc[3] = fmaf(a, v0.w, acc[3]);
        acc[4] = fmaf(a, v1.x, acc[4]);
        acc[5] = fmaf(a, v1.y, acc[5]);
        acc[6] = fmaf(a, v1.z, acc[6]);
        acc[7] = fmaf(a, v1.w, acc[7]);
    }

    const float4 bg0 = *(const float4*)(bias_g + lane * 8);
    const float4 bg1 = *(const float4*)(bias_g + lane * 8 + 4);
    float* op = out + (size_t)d * HC + lane * 8;
    *(float4*)op       = make_float4(acc[0] + bg0.x, acc[1] + bg0.y,
                                     acc[2] + bg0.z, acc[3] + bg0.w);
    *(float4*)(op + 4) = make_float4(acc[4] + bg1.x, acc[5] + bg1.y,
                                     acc[6] + bg1.z, acc[7] + bg1.w);
}

// ---------------- launch --------------------------------------------------------
extern "C" void kernel_launch(void* const* d_in, const int* in_sizes, int n_in,
                              void* d_out, int out_size) {
    const float* x   = (const float*)d_in[0];
    const int*   ei  = (const int*)d_in[1];
    const float* W1  = (const float*)d_in[2];
    const float* b1  = (const float*)d_in[3];
    const float* W2  = (const float*)d_in[4];
    const float* b2  = (const float*)d_in[5];
    const float* Wg  = (const float*)d_in[6];
    const float* att_src = (const float*)d_in[7];
    const float* att_dst = (const float*)d_in[8];
    const float* bias_g  = (const float*)d_in[9];
    float* out = (float*)d_out;

    __nv_bfloat16 *xhi, *xlo, *h1hi, *h1lo, *h2hi, *h2lo;
    __nv_bfloat16 *w1thi, *w1tlo, *w2thi, *w2tlo, *wgthi, *wgtlo;
    float* xg;
    cudaGetSymbolAddress((void**)&xhi,  g_xhi);
    cudaGetSymbolAddress((void**)&xlo,  g_xlo);
    cudaGetSymbolAddress((void**)&h1hi, g_h1hi);
    cudaGetSymbolAddress((void**)&h1lo, g_h1lo);
    cudaGetSymbolAddress((void**)&h2hi, g_h2hi);
    cudaGetSymbolAddress((void**)&h2lo, g_h2lo);
    cudaGetSymbolAddress((void**)&w1thi, g_w1thi);
    cudaGetSymbolAddress((void**)&w1tlo, g_w1tlo);
    cudaGetSymbolAddress((void**)&w2thi, g_w2thi);
    cudaGetSymbolAddress((void**)&w2tlo, g_w2tlo);
    cudaGetSymbolAddress((void**)&wgthi, g_wgthi);
    cudaGetSymbolAddress((void**)&wgtlo, g_wgtlo);
    cudaGetSymbolAddress((void**)&xg, g_xg);

    const int mblk = (Nn + 127) / 128;   // 157

    // CSR build
    init_counts_kernel<<<(Nn + 255) / 256, 256>>>();
    count_kernel<<<(Ee + 255) / 256, 256>>>(ei);
    scan_kernel<<<1, 1024>>>();
    scatter_kernel<<<(TT + 255) / 256, 256>>>(ei);

    // prep: split x, transpose+split weights
    split_kernel<<<(Nn * F_IN / 4 + 255) / 256, 256>>>(x, xhi, xlo, Nn * F_IN / 4);
    wtsplit_kernel<<<(F_IN * HID + 255) / 256, 256>>>(W1, w1thi, w1tlo, F_IN, HID);
    wtsplit_kernel<<<(HID * OUT + 255) / 256, 256>>>(W2, w2thi, w2tlo, HID, OUT);
    wtsplit_kernel<<<(OUT * HC + 255) / 256, 256>>>(Wg, wgthi, wgtlo, OUT, HC);

    // GEMM chain (bf16x3 on mma.sync.m16n8k16)
    bf16gemm<true,  true,  true ><<<dim3(1, mblk), 256>>>(
        xhi, xlo, w1thi, w1tlo, b1, nullptr, h1hi, h1lo, Nn, HID, F_IN);
    bf16gemm<false, true,  true ><<<dim3(1, mblk), 256>>>(
        h1hi, h1lo, w2thi, w2tlo, b2, nullptr, h2hi, h2lo, Nn, OUT, HID);
    bf16gemm<false, false, false><<<dim3(2, mblk), 256>>>(
        h2hi, h2lo, wgthi, wgtlo, nullptr, xg, nullptr, nullptr, Nn, HC, OUT);

    // attention coefficients
    att_kernel<<<(Nn * Hh + 7) / 8, 256>>>(att_src, att_dst);

    // fused softmax + aggregation
    gat_agg_kernel<<<(Nn + 7) / 8, 256>>>(out, bias_g);
}